// round 1
// baseline (speedup 1.0000x reference)
#include <cuda_runtime.h>
#include <math.h>

#define TOT 21330

static const int HS[5]      = {100, 50, 25, 13, 7};
static const int WS[5]      = {160, 80, 40, 20, 10};
static const int STRIDE5[5] = {8, 16, 32, 64, 128};
static const int OFFS[5]    = {0, 16000, 20000, 21000, 21260};

#define BUF_ELEMS (2 * 256 * 100 * 160)

// scratch (allocation-free contract: __device__ globals)
__device__ float g_t0[BUF_ELEMS];
__device__ float g_t1[BUF_ELEMS];
__device__ float g_t2[BUF_ELEMS];
__device__ float g_affs[3 * 512];   // per-(n,c) GN scale, slots: 0 working, 1 cls-final, 2 box-final
__device__ float g_affb[3 * 512];   // per-(n,c) GN bias
__device__ float g_sigctr[2 * TOT]; // sigmoid(centerness)

__device__ __forceinline__ float sigmoidf_(float v) {
    return 1.f / (1.f + expf(-v));
}

// Generic 3x3 SAME conv, Cin=256 fixed. Spatial tile 8x8, OC tile 64, 256 threads,
// 2 oc per thread (ocp, ocp+32), 8 pixels (one tile row) per thread.
// Input transform (GN affine + ReLU of the PREVIOUS layer) applied on SMEM load.
// mode 0: y[n,oc,h,w] = conv + bias            (tower layer, raw for GN stats)
// mode 1: out[n,pix,oc] = sigmoid(v)*sigctr    (score head, Co=80)
// mode 2: Co=5 (4 pred via w/bias, 1 ctr via w2/bias2): boxes -> out[...,80..83], sigctr side buf
__global__ __launch_bounds__(256) void conv3x3_k(
    const float* __restrict__ x,
    const float* __restrict__ w, const float* __restrict__ w2,
    const float* __restrict__ bias, const float* __restrict__ bias2,
    int co_split, int Co,
    const float* __restrict__ in_s, const float* __restrict__ in_b,
    float* __restrict__ y,
    float* __restrict__ out, float* __restrict__ sigctr,
    const float* __restrict__ scales,
    int H, int W, int mode, int level, int off, float stride_f)
{
    __shared__ float s_in[800];    // 8 ic x 10 x 10
    __shared__ float s_w[4608];    // 64 oc x 8 ic x 9

    const int tid = threadIdx.x;
    const int n = blockIdx.z;
    const int tilesW = (W + 7) >> 3;
    const int tw = blockIdx.x % tilesW;
    const int th = blockIdx.x / tilesW;
    const int h0 = th * 8, w0 = tw * 8;
    const int ocbase = blockIdx.y * 64;
    const int ocp = tid >> 3;      // 0..31
    const int row = tid & 7;       // 0..7

    float acc0[8], acc1[8];
#pragma unroll
    for (int c = 0; c < 8; c++) { acc0[c] = 0.f; acc1[c] = 0.f; }

    for (int icb = 0; icb < 256; icb += 8) {
        __syncthreads();
        // cooperative input tile load (with GN+ReLU transform of previous layer)
        for (int e = tid; e < 800; e += 256) {
            int ic = e / 100;
            int rem = e - ic * 100;
            int r = rem / 10;
            int cc = rem - r * 10;
            int gh = h0 + r - 1, gw = w0 + cc - 1;
            float v = 0.f;
            if (gh >= 0 && gh < H && gw >= 0 && gw < W) {
                v = x[(((size_t)n * 256 + icb + ic) * H + gh) * W + gw];
                if (in_s) {
                    int ci = n * 256 + icb + ic;
                    v = fmaxf(fmaf(v, in_s[ci], in_b[ci]), 0.f);
                }
            }
            s_in[e] = v;
        }
        // cooperative weight tile load (zero-pad oc >= Co)
#pragma unroll
        for (int e = tid; e < 4608; e += 256) {
            int oc = e / 72;
            int rem = e - oc * 72;
            int ic = rem / 9;
            int k = rem - ic * 9;
            int ocg = ocbase + oc;
            float v = 0.f;
            if (ocg < Co) {
                if (ocg < co_split) v = w[((size_t)ocg * 256 + icb + ic) * 9 + k];
                else                v = w2[((size_t)(ocg - co_split) * 256 + icb + ic) * 9 + k];
            }
            s_w[e] = v;
        }
        __syncthreads();

#pragma unroll
        for (int icl = 0; icl < 8; icl++) {
            float wv0[9], wv1[9];
#pragma unroll
            for (int k = 0; k < 9; k++) {
                wv0[k] = s_w[(ocp * 8 + icl) * 9 + k];
                wv1[k] = s_w[((ocp + 32) * 8 + icl) * 9 + k];
            }
            float rr[3][10];
#pragma unroll
            for (int d = 0; d < 3; d++)
#pragma unroll
                for (int c = 0; c < 10; c++)
                    rr[d][c] = s_in[icl * 100 + (row + d) * 10 + c];
#pragma unroll
            for (int c = 0; c < 8; c++) {
                float a0 = acc0[c], a1 = acc1[c];
#pragma unroll
                for (int k = 0; k < 9; k++) {
                    float iv = rr[k / 3][c + (k % 3)];
                    a0 = fmaf(wv0[k], iv, a0);
                    a1 = fmaf(wv1[k], iv, a1);
                }
                acc0[c] = a0; acc1[c] = a1;
            }
        }
    }

    // ---- epilogue ----
    const int gh = h0 + row;
    if (gh >= H) return;
    const int oc_g0 = ocbase + ocp;
    const int oc_g1 = ocbase + ocp + 32;
    const float b0 = (oc_g0 < Co) ? ((oc_g0 < co_split) ? bias[oc_g0] : bias2[oc_g0 - co_split]) : 0.f;
    const float b1 = (oc_g1 < Co) ? ((oc_g1 < co_split) ? bias[oc_g1] : bias2[oc_g1 - co_split]) : 0.f;

    if (mode == 0) {
#pragma unroll
        for (int c = 0; c < 8; c++) {
            int gw = w0 + c;
            if (gw >= W) continue;
            if (oc_g0 < Co) y[(((size_t)n * 256 + oc_g0) * H + gh) * W + gw] = acc0[c] + b0;
            if (oc_g1 < Co) y[(((size_t)n * 256 + oc_g1) * H + gh) * W + gw] = acc1[c] + b1;
        }
    } else if (mode == 1) {
#pragma unroll
        for (int c = 0; c < 8; c++) {
            int gw = w0 + c;
            if (gw >= W) continue;
            int pix = off + gh * W + gw;
            int rb = (n * TOT + pix) * 84;
            float sc = sigctr[n * TOT + pix];
            if (oc_g0 < Co) out[rb + oc_g0] = sc * sigmoidf_(acc0[c] + b0);
            if (oc_g1 < Co) out[rb + oc_g1] = sc * sigmoidf_(acc1[c] + b1);
        }
    } else { // mode 2: oc 0..3 = pred (box deltas), oc 4 = centerness
        if (oc_g0 < 5) {
            float sl = scales[level];
#pragma unroll
            for (int c = 0; c < 8; c++) {
                int gw = w0 + c;
                if (gw >= W) continue;
                float v = acc0[c] + b0;
                int pix = off + gh * W + gw;
                if (oc_g0 == 4) {
                    sigctr[n * TOT + pix] = sigmoidf_(v);
                } else {
                    int rb = (n * TOT + pix) * 84;
                    float rg = fmaxf(v * sl, 0.f) * stride_f;
                    float sh = (oc_g0 & 1) ? (float)gh * stride_f : (float)gw * stride_f;
                    out[rb + 80 + oc_g0] = (oc_g0 < 2) ? (sh - rg) : (sh + rg);
                }
            }
        }
    }
}

// GroupNorm stats: 64 blocks = (n, group). Folds mean/rstd/gamma/beta into
// per-(n,channel) affine consumed by the NEXT conv's input transform.
__global__ __launch_bounds__(256) void gn_stats_k(
    const float* __restrict__ y,
    const float* __restrict__ gw, const float* __restrict__ gb,
    float* __restrict__ osc, float* __restrict__ obi,
    int H, int W)
{
    const int tid = threadIdx.x;
    const int n = blockIdx.x >> 5;
    const int g = blockIdx.x & 31;
    const int HW = H * W;
    const int cnt = 8 * HW;
    const float* p = y + ((size_t)n * 256 + g * 8) * (size_t)HW;

    float s = 0.f, q = 0.f;
    for (int i = tid; i < cnt; i += 256) {
        float v = p[i];
        s += v;
        q += v * v;
    }
    __shared__ float ss[256], sq[256];
    ss[tid] = s; sq[tid] = q;
    __syncthreads();
    for (int k = 128; k > 0; k >>= 1) {
        if (tid < k) { ss[tid] += ss[tid + k]; sq[tid] += sq[tid + k]; }
        __syncthreads();
    }
    if (tid < 8) {
        float inv = 1.f / (float)cnt;
        float mean = ss[0] * inv;
        float var = sq[0] * inv - mean * mean;
        float rstd = rsqrtf(var + 1e-5f);
        int c = g * 8 + tid;
        float sc = gw[c] * rstd;
        osc[n * 256 + c] = sc;
        obi[n * 256 + c] = gb[c] - mean * sc;
    }
}

extern "C" void kernel_launch(void* const* d_in, const int* in_sizes, int n_in,
                              void* d_out, int out_size)
{
    (void)in_sizes; (void)n_in; (void)out_size;

    const float* feats[5];
    for (int i = 0; i < 5; i++) feats[i] = (const float*)d_in[i];
    const float* cls_w  = (const float*)d_in[5];
    const float* cls_b  = (const float*)d_in[6];
    const float* cls_gw = (const float*)d_in[7];
    const float* cls_gb = (const float*)d_in[8];
    const float* box_w  = (const float*)d_in[9];
    const float* box_b  = (const float*)d_in[10];
    const float* box_gw = (const float*)d_in[11];
    const float* box_gb = (const float*)d_in[12];
    const float* score_w = (const float*)d_in[13];
    const float* score_b = (const float*)d_in[14];
    const float* pred_w  = (const float*)d_in[15];
    const float* pred_b  = (const float*)d_in[16];
    const float* ctr_w   = (const float*)d_in[17];
    const float* ctr_b   = (const float*)d_in[18];
    const float* scales  = (const float*)d_in[19];
    float* out = (float*)d_out;

    float *t0, *t1, *t2, *affs, *affb, *sct;
    cudaGetSymbolAddress((void**)&t0, g_t0);
    cudaGetSymbolAddress((void**)&t1, g_t1);
    cudaGetSymbolAddress((void**)&t2, g_t2);
    cudaGetSymbolAddress((void**)&affs, g_affs);
    cudaGetSymbolAddress((void**)&affb, g_affb);
    cudaGetSymbolAddress((void**)&sct, g_sigctr);

    const int BIG = 1 << 30;
    dim3 blk(256);

    for (int l = 0; l < 5; l++) {
        int H = HS[l], W = WS[l];
        int tiles = ((W + 7) / 8) * ((H + 7) / 8);
        dim3 gridc(tiles, 4, 2);   // Co=256 -> 4 oc tiles

        float* pp[2][2] = { { t0, t1 }, { t0, t2 } };
        float* finals[2];

        for (int t = 0; t < 2; t++) {
            const float* cur = feats[l];
            const float* W_ = t ? box_w : cls_w;
            const float* B_ = t ? box_b : cls_b;
            const float* GW = t ? box_gw : cls_gw;
            const float* GB = t ? box_gb : cls_gb;
            for (int i = 0; i < 4; i++) {
                float* dst = pp[t][i & 1];
                const float* is = (i == 0) ? nullptr : affs;  // slot 0
                const float* ib = (i == 0) ? nullptr : affb;
                conv3x3_k<<<gridc, blk>>>(
                    cur, W_ + (size_t)i * 256 * 256 * 9, nullptr,
                    B_ + i * 256, nullptr, BIG, 256,
                    is, ib, dst, nullptr, nullptr, nullptr,
                    H, W, /*mode=*/0, l, 0, 0.f);
                int slot = (i == 3) ? (t + 1) : 0;  // final affine persists per tower
                gn_stats_k<<<64, blk>>>(dst, GW + i * 256, GB + i * 256,
                                        affs + slot * 512, affb + slot * 512, H, W);
                cur = dst;
            }
            finals[t] = pp[t][1];
        }

        // box head first (writes boxes + sigmoid(ctr)), then cls head (needs sigctr)
        dim3 gridb(tiles, 1, 2);
        conv3x3_k<<<gridb, blk>>>(
            finals[1], pred_w, ctr_w, pred_b, ctr_b, /*split=*/4, /*Co=*/5,
            affs + 2 * 512, affb + 2 * 512, nullptr, out, sct, scales,
            H, W, /*mode=*/2, l, OFFS[l], (float)STRIDE5[l]);

        dim3 grids(tiles, 2, 2);
        conv3x3_k<<<grids, blk>>>(
            finals[0], score_w, nullptr, score_b, nullptr, BIG, /*Co=*/80,
            affs + 1 * 512, affb + 1 * 512, nullptr, out, sct, nullptr,
            H, W, /*mode=*/1, l, OFFS[l], 0.f);
    }
}

// round 2
// speedup vs baseline: 1.0406x; 1.0406x over previous
#include <cuda_runtime.h>
#include <math.h>

#define TOT 21330
typedef unsigned long long ull;

static const int HS[5]      = {100, 50, 25, 13, 7};
static const int WS[5]      = {160, 80, 40, 20, 10};
static const int STRIDE5[5] = {8, 16, 32, 64, 128};
static const int OFFS[5]    = {0, 16000, 20000, 21000, 21260};
static const int LOFF[5]    = {0, 512*16000, 512*20000, 512*21000, 512*21260};

__constant__ int d_HW[5] = {16000, 4000, 1000, 260, 70};

#define LVL_ELEMS (512 * 21330)
// scratch: [tower][pingpong]
__device__ float g_buf[4][LVL_ELEMS];
__device__ float g_affs[10 * 512];       // per (tower,level) folded GN scale
__device__ float g_affb[10 * 512];       // per (tower,level) folded GN bias
__device__ float g_part[10 * 64 * 8 * 2]; // GN partial sums [(t,l)][n*32+g][split][2]
__device__ float g_sigctr[2 * TOT];

__device__ __forceinline__ float sigmoidf_(float v) { return 1.f / (1.f + expf(-v)); }

#define FMA2(d, a, b, c) \
    asm("fma.rn.f32x2 %0, %1, %2, %3;" : "=l"(d) : "l"(a), "l"(b), "l"(c))
#define PACKDUP(d, x) \
    asm("mov.b64 %0, {%1, %1};" : "=l"(d) : "r"(__float_as_uint(x)))
#define UNPACK2(lo, hi, v) \
    asm("mov.b64 {%0, %1}, %2;" : "=r"(lo), "=r"(hi) : "l"(v))

// 3x3 SAME conv, Cin=256. Tile: 8x8 spatial, 128 oc, 256 threads.
// Thread = (ocq 0..31, row 0..7): oc {2q,2q+1,64+2q,64+2q+1} x 8 pixels.
// f32x2 packed FMA over oc pairs; weights LDS.64 from transposed smem.
// mode 0: tower layer (raw conv+bias out for GN); mode 1: cls head; mode 2: box+ctr head.
__global__ __launch_bounds__(256) void conv3x3_k(
    const float* __restrict__ x,
    const float* __restrict__ w, const float* __restrict__ w2,
    const float* __restrict__ bias, const float* __restrict__ bias2,
    int co_split, int Co,
    const float* __restrict__ in_s, const float* __restrict__ in_b,
    float* __restrict__ y,
    float* __restrict__ out, float* __restrict__ sigctr,
    const float* __restrict__ scales,
    int H, int W, int mode, int level, int off, float stride_f)
{
    __shared__ __align__(16) float s_in[1600];      // 8 ic x 10 r x 20 (padded)
    __shared__ __align__(16) float s_w[72 * 130];   // [ic*9+k][oc 0..127], pad 130

    const int tid = threadIdx.x;
    const int n = blockIdx.z;
    const int tilesW = (W + 7) >> 3;
    const int tw = blockIdx.x % tilesW;
    const int th = blockIdx.x / tilesW;
    const int h0 = th * 8, w0 = tw * 8;
    const int ocbase = blockIdx.y * 128;
    const int ocq = tid >> 3;   // 0..31
    const int row = tid & 7;    // 0..7

    ull accA[8], accB[8];
#pragma unroll
    for (int c = 0; c < 8; c++) { accA[c] = 0ull; accB[c] = 0ull; }

    for (int icb = 0; icb < 256; icb += 8) {
        __syncthreads();
        // input tile (GN affine + ReLU of previous layer applied on load)
#pragma unroll
        for (int e0 = 0; e0 < 800; e0 += 256) {
            int e = e0 + tid;
            if (e < 800) {
                int ic = e / 100;
                int rem = e - ic * 100;
                int r = rem / 10;
                int cc = rem - r * 10;
                int gh = h0 + r - 1, gw = w0 + cc - 1;
                float v = 0.f;
                if (gh >= 0 && gh < H && gw >= 0 && gw < W) {
                    v = x[(((size_t)n * 256 + icb + ic) * H + gh) * W + gw];
                    if (in_s) {
                        int ci = n * 256 + icb + ic;
                        v = fmaxf(fmaf(v, in_s[ci], in_b[ci]), 0.f);
                    }
                }
                s_in[ic * 200 + r * 20 + cc] = v;
            }
        }
        // weights: coalesced global read, transposed store [ick][oc]
#pragma unroll
        for (int e0 = 0; e0 < 9216; e0 += 256) {
            int e = e0 + tid;
            int oc = e / 72;
            int rem = e - oc * 72;
            int ic = rem / 9;
            int k = rem - ic * 9;
            int ocg = ocbase + oc;
            float v = 0.f;
            if (ocg < Co) {
                if (ocg < co_split) v = w[((size_t)ocg * 256 + icb + ic) * 9 + k];
                else                v = w2[((size_t)(ocg - co_split) * 256 + icb + ic) * 9 + k];
            }
            s_w[(ic * 9 + k) * 130 + oc] = v;
        }
        __syncthreads();

        const ull* wp = (const ull*)s_w;
#pragma unroll 1
        for (int icl = 0; icl < 8; icl++) {
#pragma unroll
            for (int d = 0; d < 3; d++) {
                const float* rp = s_in + icl * 200 + (row + d) * 20;
                float4 ra = *(const float4*)rp;
                float4 rb = *(const float4*)(rp + 4);
                float2 rc = *(const float2*)(rp + 8);
                float rv[10] = {ra.x, ra.y, ra.z, ra.w, rb.x, rb.y, rb.z, rb.w, rc.x, rc.y};
                ull dup[10];
#pragma unroll
                for (int j = 0; j < 10; j++) PACKDUP(dup[j], rv[j]);
#pragma unroll
                for (int kx = 0; kx < 3; kx++) {
                    int k = d * 3 + kx;
                    ull wA = wp[(icl * 9 + k) * 65 + ocq];
                    ull wB = wp[(icl * 9 + k) * 65 + 32 + ocq];
#pragma unroll
                    for (int c = 0; c < 8; c++) {
                        FMA2(accA[c], wA, dup[c + kx], accA[c]);
                        FMA2(accB[c], wB, dup[c + kx], accB[c]);
                    }
                }
            }
        }
    }

    // ---- epilogue ----
    const int gh = h0 + row;
    if (gh >= H) return;
    int ocl[4];
    ocl[0] = ocbase + 2 * ocq;     ocl[1] = ocl[0] + 1;
    ocl[2] = ocbase + 64 + 2 * ocq; ocl[3] = ocl[2] + 1;
    float bv[4];
#pragma unroll
    for (int t4 = 0; t4 < 4; t4++) {
        int oc = ocl[t4];
        bv[t4] = (oc < Co) ? ((oc < co_split) ? bias[oc] : bias2[oc - co_split]) : 0.f;
    }

#pragma unroll
    for (int c = 0; c < 8; c++) {
        int gw = w0 + c;
        if (gw >= W) continue;
        unsigned u0, u1, u2, u3;
        UNPACK2(u0, u1, accA[c]);
        UNPACK2(u2, u3, accB[c]);
        float v4[4] = {__uint_as_float(u0), __uint_as_float(u1),
                       __uint_as_float(u2), __uint_as_float(u3)};
        if (mode == 0) {
#pragma unroll
            for (int t4 = 0; t4 < 4; t4++) {
                int oc = ocl[t4];
                if (oc < Co)
                    y[(((size_t)n * 256 + oc) * H + gh) * W + gw] = v4[t4] + bv[t4];
            }
        } else if (mode == 1) {
            int pix = off + gh * W + gw;
            int rb = (n * TOT + pix) * 84;
            float sc = sigctr[n * TOT + pix];
#pragma unroll
            for (int t4 = 0; t4 < 4; t4++) {
                int oc = ocl[t4];
                if (oc < Co) out[rb + oc] = sc * sigmoidf_(v4[t4] + bv[t4]);
            }
        } else {
            int pix = off + gh * W + gw;
            float sl = scales[level];
#pragma unroll
            for (int t4 = 0; t4 < 4; t4++) {
                int oc = ocl[t4];
                if (oc >= 5) continue;
                float v = v4[t4] + bv[t4];
                if (oc == 4) {
                    sigctr[n * TOT + pix] = sigmoidf_(v);
                } else {
                    int rb = (n * TOT + pix) * 84;
                    float rg = fmaxf(v * sl, 0.f) * stride_f;
                    float sh = (oc & 1) ? (float)gh * stride_f : (float)gw * stride_f;
                    out[rb + 80 + oc] = (oc < 2) ? (sh - rg) : (sh + rg);
                }
            }
        }
    }
}

// GN partial sums: grid (64 = n*32+g, 8 splits), 256 threads. No atomics.
__global__ __launch_bounds__(256) void gnp_k(
    const float* __restrict__ y, float* __restrict__ part, int HW)
{
    const int tid = threadIdx.x;
    const int bx = blockIdx.x;
    const int s = blockIdx.y;
    const int cnt = 8 * HW;
    const float* p = y + (size_t)bx * cnt;
    int chunk = (cnt + 7) >> 3;
    int beg = s * chunk;
    int end = min(cnt, beg + chunk);

    float sm = 0.f, sq = 0.f;
    for (int i = beg + tid; i < end; i += 256) {
        float v = p[i];
        sm += v; sq += v * v;
    }
    __shared__ float ss[256], sv[256];
    ss[tid] = sm; sv[tid] = sq;
    __syncthreads();
    for (int k = 128; k > 0; k >>= 1) {
        if (tid < k) { ss[tid] += ss[tid + k]; sv[tid] += sv[tid + k]; }
        __syncthreads();
    }
    if (tid == 0) {
        part[(bx * 8 + s) * 2 + 0] = ss[0];
        part[(bx * 8 + s) * 2 + 1] = sv[0];
    }
}

// Finalize all 10 (tower,level) GN affines for layer depth i. grid=10, 512 thr.
__global__ __launch_bounds__(512) void fin_k(
    const float* __restrict__ cls_gw, const float* __restrict__ cls_gb,
    const float* __restrict__ box_gw, const float* __restrict__ box_gb, int i)
{
    const int b = blockIdx.x;
    const int t = b / 5, l = b % 5;
    const int tid = threadIdx.x;
    const int n = tid >> 8, c = tid & 255, g = c >> 3;
    const float* part = g_part + (size_t)b * 1024;
    float sm = 0.f, sq = 0.f;
#pragma unroll
    for (int s = 0; s < 8; s++) {
        sm += part[((n * 32 + g) * 8 + s) * 2 + 0];
        sq += part[((n * 32 + g) * 8 + s) * 2 + 1];
    }
    float inv = 1.f / (float)(8 * d_HW[l]);
    float mean = sm * inv;
    float var = sq * inv - mean * mean;
    float rstd = rsqrtf(var + 1e-5f);
    const float* gw = t ? box_gw : cls_gw;
    const float* gb = t ? box_gb : cls_gb;
    float sc = gw[i * 256 + c] * rstd;
    g_affs[b * 512 + tid] = sc;
    g_affb[b * 512 + tid] = gb[i * 256 + c] - mean * sc;
}

extern "C" void kernel_launch(void* const* d_in, const int* in_sizes, int n_in,
                              void* d_out, int out_size)
{
    (void)in_sizes; (void)n_in; (void)out_size;

    const float* feats[5];
    for (int i = 0; i < 5; i++) feats[i] = (const float*)d_in[i];
    const float* cls_w  = (const float*)d_in[5];
    const float* cls_b  = (const float*)d_in[6];
    const float* cls_gw = (const float*)d_in[7];
    const float* cls_gb = (const float*)d_in[8];
    const float* box_w  = (const float*)d_in[9];
    const float* box_b  = (const float*)d_in[10];
    const float* box_gw = (const float*)d_in[11];
    const float* box_gb = (const float*)d_in[12];
    const float* score_w = (const float*)d_in[13];
    const float* score_b = (const float*)d_in[14];
    const float* pred_w  = (const float*)d_in[15];
    const float* pred_b  = (const float*)d_in[16];
    const float* ctr_w   = (const float*)d_in[17];
    const float* ctr_b   = (const float*)d_in[18];
    const float* scales  = (const float*)d_in[19];
    float* out = (float*)d_out;

    float *buf, *affs, *affb, *part, *sct;
    cudaGetSymbolAddress((void**)&buf, g_buf);
    cudaGetSymbolAddress((void**)&affs, g_affs);
    cudaGetSymbolAddress((void**)&affb, g_affb);
    cudaGetSymbolAddress((void**)&part, g_part);
    cudaGetSymbolAddress((void**)&sct, g_sigctr);

    const int BIG = 1 << 30;
    dim3 blk(256);

    // Layer-depth-batched schedule: launch idx 5 = box tower conv, level 0 (full size)
    for (int i = 0; i < 4; i++) {
        for (int t = 0; t < 2; t++) {
            const float* W_ = t ? box_w : cls_w;
            const float* B_ = t ? box_b : cls_b;
            for (int l = 0; l < 5; l++) {
                int H = HS[l], Wd = WS[l];
                int tiles = ((Wd + 7) / 8) * ((H + 7) / 8);
                dim3 gridc(tiles, 2, 2);
                const float* in = (i == 0) ? feats[l]
                    : buf + (size_t)(t * 2 + ((i + 1) & 1)) * LVL_ELEMS + LOFF[l];
                float* dst = buf + (size_t)(t * 2 + (i & 1)) * LVL_ELEMS + LOFF[l];
                const float* is = (i == 0) ? nullptr : affs + (t * 5 + l) * 512;
                const float* ib = (i == 0) ? nullptr : affb + (t * 5 + l) * 512;
                conv3x3_k<<<gridc, blk>>>(
                    in, W_ + (size_t)i * 256 * 256 * 9, nullptr,
                    B_ + i * 256, nullptr, BIG, 256,
                    is, ib, dst, nullptr, nullptr, nullptr,
                    H, Wd, 0, l, 0, 0.f);
            }
        }
        for (int t = 0; t < 2; t++)
            for (int l = 0; l < 5; l++) {
                float* dst = buf + (size_t)(t * 2 + (i & 1)) * LVL_ELEMS + LOFF[l];
                dim3 gridg(64, 8);
                gnp_k<<<gridg, blk>>>(dst, part + (t * 5 + l) * 1024, HS[l] * WS[l]);
            }
        fin_k<<<10, 512>>>(cls_gw, cls_gb, box_gw, box_gb, i);
    }

    // heads: box first (writes boxes + sigctr), then cls (reads sigctr)
    for (int l = 0; l < 5; l++) {
        int H = HS[l], Wd = WS[l];
        int tiles = ((Wd + 7) / 8) * ((H + 7) / 8);
        dim3 gridb(tiles, 1, 2);
        const float* fin_box = buf + (size_t)(1 * 2 + 1) * LVL_ELEMS + LOFF[l];
        conv3x3_k<<<gridb, blk>>>(
            fin_box, pred_w, ctr_w, pred_b, ctr_b, 4, 5,
            affs + (5 + l) * 512, affb + (5 + l) * 512, nullptr, out, sct, scales,
            H, Wd, 2, l, OFFS[l], (float)STRIDE5[l]);
    }
    for (int l = 0; l < 5; l++) {
        int H = HS[l], Wd = WS[l];
        int tiles = ((Wd + 7) / 8) * ((H + 7) / 8);
        dim3 grids(tiles, 1, 2);
        const float* fin_cls = buf + (size_t)(0 * 2 + 1) * LVL_ELEMS + LOFF[l];
        conv3x3_k<<<grids, blk>>>(
            fin_cls, score_w, nullptr, score_b, nullptr, BIG, 80,
            affs + (0 * 5 + l) * 512, affb + (0 * 5 + l) * 512, nullptr, out, sct, nullptr,
            H, Wd, 1, l, OFFS[l], 0.f);
    }
}

// round 3
// speedup vs baseline: 2.0406x; 1.9609x over previous
#include <cuda_runtime.h>
#include <math.h>

#define TOT 21330
typedef unsigned long long ull;

__constant__ int   c_tb[6]  = {0, 260, 330, 350, 356, 358};
__constant__ int   c_H[5]   = {100, 50, 25, 13, 7};
__constant__ int   c_W[5]   = {160, 80, 40, 20, 10};
__constant__ int   c_twc[5] = {20, 10, 5, 3, 2};
__constant__ int   c_off[5] = {0, 16000, 20000, 21000, 21260};
__constant__ float c_str[5] = {8.f, 16.f, 32.f, 64.f, 128.f};
__constant__ int   c_HW[5]  = {16000, 4000, 1000, 260, 70};

static const int HS[5]   = {100, 50, 25, 13, 7};
static const int WS[5]   = {160, 80, 40, 20, 10};
static const int OFFS[5] = {0, 16000, 20000, 21000, 21260};

#define LVL_ELEMS (512 * 21330)
__device__ float g_buf[4][LVL_ELEMS];     // [tower*2+pingpong]
__device__ float g_affs[10 * 512];
__device__ float g_affb[10 * 512];
__device__ float g_part[10 * 64 * 4 * 2];
__device__ float g_sigctr[2 * TOT];

struct P5  { const float* p[5]; };
struct P5o { float* p[5]; };

__device__ __forceinline__ float sigmoidf_(float v) { return 1.f / (1.f + expf(-v)); }

#define FMA2(d, a, b, c) \
    asm("fma.rn.f32x2 %0, %1, %2, %3;" : "=l"(d) : "l"(a), "l"(b), "l"(c))
#define PACKDUP(d, x) \
    asm("mov.b64 %0, {%1, %1};" : "=l"(d) : "r"(__float_as_uint(x)))
#define UNPACK2(lo, hi, v) \
    asm("mov.b64 {%0, %1}, %2;" : "=r"(lo), "=r"(hi) : "l"(v))

// 3x3 SAME conv, Cin=256. Mega-grid: blockIdx.x = flattened (level,tile),
// 8x8 spatial tile, 64-oc tile, 256 threads, thread=(ocq,row): oc pair (2q,2q+1) x 8 px.
// f32x2 packed FMA. GN-affine+ReLU of previous layer fused on input load.
// heads=0: tower layer (mode 0). heads=1: by<2 -> cls head (mode 1), by==2 -> box+ctr (mode 2).
__global__ __launch_bounds__(256, 2) void convm_k(
    P5 inC, P5 inB, P5o outC, P5o outB,
    const float* __restrict__ wC, const float* __restrict__ wB,
    const float* __restrict__ bC, const float* __restrict__ bB,
    const float* __restrict__ w2, const float* __restrict__ b2,
    const float* __restrict__ affs, const float* __restrict__ affb,
    const float* __restrict__ scales,
    float* __restrict__ out, float* __restrict__ sigctr,
    int heads, int tsel)
{
    __shared__ __align__(16) float s_in[8 * 120];   // 8 ic x 10 r x 12 (pad)
    __shared__ __align__(16) float s_w[72 * 66];    // [ic*9+k][oc 0..63], pad 66

    const int tid = threadIdx.x;
    const int bx = blockIdx.x, by = blockIdx.y, bz = blockIdx.z;
    int l = 0;
#pragma unroll
    for (int q = 1; q < 5; q++) if (bx >= c_tb[q]) l = q;
    const int tile = bx - c_tb[l];
    const int H = c_H[l], W = c_W[l];
    const int tw = tile % c_twc[l], th = tile / c_twc[l];
    const int h0 = th * 8, w0 = tw * 8;

    int t, n, ocbase, Co, co_split, mode;
    if (!heads) { t = tsel; n = bz; ocbase = by * 64; Co = 256; co_split = 1 << 30; mode = 0; }
    else {
        n = bz;
        if (by < 2) { t = 0; ocbase = by * 64; Co = 80; co_split = 1 << 30; mode = 1; }
        else        { t = 1; ocbase = 0;       Co = 5;  co_split = 4;       mode = 2; }
    }
    const int slot = t * 5 + l;
    const float* x    = t ? inB.p[l] : inC.p[l];
    const float* w    = t ? wB : wC;
    const float* bias = t ? bB : bC;
    const float* isc  = affs ? affs + slot * 512 + n * 256 : nullptr;
    const float* ibi  = affs ? affb + slot * 512 + n * 256 : nullptr;

    const int ocq = tid >> 3, row = tid & 7;

    ull acc[8];
#pragma unroll
    for (int c = 0; c < 8; c++) acc[c] = 0ull;

    for (int icb = 0; icb < 256; icb += 8) {
        __syncthreads();
        // input tile (prev-layer GN affine + ReLU fused)
#pragma unroll
        for (int it = 0; it < 4; it++) {
            int e = tid + it * 256;
            if (e < 800) {
                int ic = e / 100, rem = e - ic * 100;
                int r = rem / 10, cc = rem - r * 10;
                int gh = h0 + r - 1, gw = w0 + cc - 1;
                float v = 0.f;
                if (gh >= 0 && gh < H && gw >= 0 && gw < W) {
                    v = x[(((size_t)n * 256 + icb + ic) * H + gh) * W + gw];
                    if (isc) { int ci = icb + ic; v = fmaxf(fmaf(v, isc[ci], ibi[ci]), 0.f); }
                }
                s_in[ic * 120 + r * 12 + cc] = v;
            }
        }
        // weights: coalesced LDG (72 contiguous per oc per chunk), transposed STS
#pragma unroll 3
        for (int it = 0; it < 18; it++) {
            int e = tid + it * 256;
            int oc = e / 72;
            int rem = e - oc * 72;
            int ocg = ocbase + oc;
            float v = 0.f;
            if (ocg < Co) {
                const float* wr = (ocg < co_split) ? (w + (size_t)ocg * 2304)
                                                   : (w2 + (size_t)(ocg - co_split) * 2304);
                v = wr[icb * 9 + rem];
            }
            s_w[rem * 66 + oc] = v;
        }
        __syncthreads();

        const ull* wq = (const ull*)s_w;
#pragma unroll 1
        for (int icl = 0; icl < 8; icl++) {
#pragma unroll
            for (int d = 0; d < 3; d++) {
                const float* rp = s_in + icl * 120 + (row + d) * 12;
                float4 ra = *(const float4*)rp;
                float4 rb = *(const float4*)(rp + 4);
                float2 rc = *(const float2*)(rp + 8);
                float rv[10] = {ra.x, ra.y, ra.z, ra.w, rb.x, rb.y, rb.z, rb.w, rc.x, rc.y};
                ull dup[10];
#pragma unroll
                for (int j = 0; j < 10; j++) PACKDUP(dup[j], rv[j]);
#pragma unroll
                for (int kx = 0; kx < 3; kx++) {
                    ull wv = wq[(icl * 9 + d * 3 + kx) * 33 + ocq];
#pragma unroll
                    for (int c = 0; c < 8; c++) FMA2(acc[c], wv, dup[c + kx], acc[c]);
                }
            }
        }
    }

    // ---- epilogue ----
    const int gh = h0 + row;
    if (gh >= H) return;
    const int og0 = ocbase + 2 * ocq, og1 = og0 + 1;
    float b0 = 0.f, b1 = 0.f;
    if (og0 < Co) b0 = (og0 < co_split) ? bias[og0] : b2[og0 - co_split];
    if (og1 < Co) b1 = (og1 < co_split) ? bias[og1] : b2[og1 - co_split];
    float lo[8], hi[8];
#pragma unroll
    for (int c = 0; c < 8; c++) {
        unsigned u0, u1; UNPACK2(u0, u1, acc[c]);
        lo[c] = __uint_as_float(u0) + b0;
        hi[c] = __uint_as_float(u1) + b1;
    }

    if (mode == 0) {
        float* yb = t ? outB.p[l] : outC.p[l];
        float* p0 = yb + (((size_t)n * 256 + og0) * H + gh) * W + w0;
        float* p1 = yb + (((size_t)n * 256 + og1) * H + gh) * W + w0;
        if ((W & 3) == 0 && w0 + 8 <= W) {
            *(float4*)p0       = make_float4(lo[0], lo[1], lo[2], lo[3]);
            *(float4*)(p0 + 4) = make_float4(lo[4], lo[5], lo[6], lo[7]);
            *(float4*)p1       = make_float4(hi[0], hi[1], hi[2], hi[3]);
            *(float4*)(p1 + 4) = make_float4(hi[4], hi[5], hi[6], hi[7]);
        } else {
#pragma unroll
            for (int c = 0; c < 8; c++)
                if (w0 + c < W) { p0[c] = lo[c]; p1[c] = hi[c]; }
        }
    } else if (mode == 1) {
#pragma unroll
        for (int c = 0; c < 8; c++) {
            int gw = w0 + c; if (gw >= W) continue;
            int pix = c_off[l] + gh * W + gw;
            size_t rb = ((size_t)n * TOT + pix) * 84;
            if (og0 < Co) out[rb + og0] = sigmoidf_(lo[c]);
            if (og1 < Co) out[rb + og1] = sigmoidf_(hi[c]);
        }
    } else {
        float sl = scales[l];
        float st = c_str[l];
#pragma unroll
        for (int c = 0; c < 8; c++) {
            int gw = w0 + c; if (gw >= W) continue;
            int pix = c_off[l] + gh * W + gw;
            size_t rb = ((size_t)n * TOT + pix) * 84;
            if (og0 < 4) {
                float rg = fmaxf(lo[c] * sl, 0.f) * st;
                float sh = (og0 & 1) ? gh * st : gw * st;
                out[rb + 80 + og0] = (og0 < 2) ? sh - rg : sh + rg;
            }
            if (og1 < 4) {
                float rg = fmaxf(hi[c] * sl, 0.f) * st;
                float sh = (og1 & 1) ? gh * st : gw * st;
                out[rb + 80 + og1] = (og1 < 2) ? sh - rg : sh + rg;
            }
            if (og0 == 4) sigctr[n * TOT + pix] = sigmoidf_(lo[c]);
        }
    }
}

// GN partial sums over mega-grid: x = (t,l)*64 + n*32+g, y = split 0..3
__global__ __launch_bounds__(256) void gnpm_k(const float* __restrict__ buf, int pp)
{
    const int tid = threadIdx.x;
    const int b = blockIdx.x >> 6;
    const int ng = blockIdx.x & 63;
    const int s = blockIdx.y;
    const int t = b / 5, l = b % 5;
    const int nn = ng >> 5, g = ng & 31;
    const int HW = c_HW[l];
    const float* p = buf + (size_t)(t * 2 + pp) * LVL_ELEMS + (size_t)512 * c_off[l]
                   + ((size_t)nn * 256 + g * 8) * HW;
    int cnt = 8 * HW;
    int chunk = (cnt + 3) >> 2;
    int beg = s * chunk, end = min(cnt, beg + chunk);

    float sm = 0.f, sq = 0.f;
    for (int i = beg + tid; i < end; i += 256) { float v = p[i]; sm += v; sq += v * v; }
    __shared__ float ss[256], sv[256];
    ss[tid] = sm; sv[tid] = sq;
    __syncthreads();
    for (int k = 128; k > 0; k >>= 1) {
        if (tid < k) { ss[tid] += ss[tid + k]; sv[tid] += sv[tid + k]; }
        __syncthreads();
    }
    if (tid == 0) {
        g_part[((b * 64 + ng) * 4 + s) * 2 + 0] = ss[0];
        g_part[((b * 64 + ng) * 4 + s) * 2 + 1] = sv[0];
    }
}

// Finalize all 10 (tower,level) GN affines for depth i
__global__ __launch_bounds__(512) void fin_k(
    const float* __restrict__ cgw, const float* __restrict__ cgb,
    const float* __restrict__ bgw, const float* __restrict__ bgb, int i)
{
    const int b = blockIdx.x;
    const int t = b / 5, l = b % 5;
    const int tid = threadIdx.x;
    const int nn = tid >> 8, c = tid & 255, g = c >> 3;
    float sm = 0.f, sq = 0.f;
#pragma unroll
    for (int s = 0; s < 4; s++) {
        sm += g_part[((b * 64 + nn * 32 + g) * 4 + s) * 2 + 0];
        sq += g_part[((b * 64 + nn * 32 + g) * 4 + s) * 2 + 1];
    }
    float inv = 1.f / (8.f * (float)c_HW[l]);
    float mean = sm * inv;
    float var = sq * inv - mean * mean;
    float rstd = rsqrtf(var + 1e-5f);
    const float* gw = t ? bgw : cgw;
    const float* gb = t ? bgb : cgb;
    float sc = gw[i * 256 + c] * rstd;
    g_affs[b * 512 + tid] = sc;
    g_affb[b * 512 + tid] = gb[i * 256 + c] - mean * sc;
}

// scores *= sigmoid(ctr): one block per output row
__global__ void mulfin_k(float* __restrict__ out, const float* __restrict__ sigctr)
{
    int p = blockIdx.x;
    float s = sigctr[p];
    float* o = out + (size_t)p * 84;
    for (int c = threadIdx.x; c < 80; c += 96) o[c] *= s;
}

extern "C" void kernel_launch(void* const* d_in, const int* in_sizes, int n_in,
                              void* d_out, int out_size)
{
    (void)in_sizes; (void)n_in; (void)out_size;

    const float* feats[5];
    for (int i = 0; i < 5; i++) feats[i] = (const float*)d_in[i];
    const float* cls_w  = (const float*)d_in[5];
    const float* cls_b  = (const float*)d_in[6];
    const float* cls_gw = (const float*)d_in[7];
    const float* cls_gb = (const float*)d_in[8];
    const float* box_w  = (const float*)d_in[9];
    const float* box_b  = (const float*)d_in[10];
    const float* box_gw = (const float*)d_in[11];
    const float* box_gb = (const float*)d_in[12];
    const float* score_w = (const float*)d_in[13];
    const float* score_b = (const float*)d_in[14];
    const float* pred_w  = (const float*)d_in[15];
    const float* pred_b  = (const float*)d_in[16];
    const float* ctr_w   = (const float*)d_in[17];
    const float* ctr_b   = (const float*)d_in[18];
    const float* scales  = (const float*)d_in[19];
    float* out = (float*)d_out;

    float *bufp, *affs, *affb, *sct;
    cudaGetSymbolAddress((void**)&bufp, g_buf);
    cudaGetSymbolAddress((void**)&affs, g_affs);
    cudaGetSymbolAddress((void**)&affb, g_affb);
    cudaGetSymbolAddress((void**)&sct, g_sigctr);

    auto lvl = [&](int t, int pp, int l) {
        return bufp + (size_t)(t * 2 + pp) * LVL_ELEMS + (size_t)512 * OFFS[l];
    };

    dim3 blk(256);
    P5o onull{};

    for (int i = 0; i < 4; i++) {
        P5 inC, inB;
        P5o outC, outB;
        for (int l = 0; l < 5; l++) {
            inC.p[l] = (i == 0) ? feats[l] : lvl(0, (i - 1) & 1, l);
            inB.p[l] = (i == 0) ? feats[l] : lvl(1, (i - 1) & 1, l);
            outC.p[l] = lvl(0, i & 1, l);
            outB.p[l] = lvl(1, i & 1, l);
        }
        const float* as = i ? affs : nullptr;
        const float* ab = i ? affb : nullptr;
        dim3 gridc(358, 4, 2);
        convm_k<<<gridc, blk>>>(inC, inB, outC, outB,
            cls_w + (size_t)i * 589824, box_w + (size_t)i * 589824,
            cls_b + i * 256, box_b + i * 256, nullptr, nullptr,
            as, ab, nullptr, nullptr, nullptr, 0, /*tsel=*/0);
        convm_k<<<gridc, blk>>>(inC, inB, outC, outB,
            cls_w + (size_t)i * 589824, box_w + (size_t)i * 589824,
            cls_b + i * 256, box_b + i * 256, nullptr, nullptr,
            as, ab, nullptr, nullptr, nullptr, 0, /*tsel=*/1);
        dim3 gridg(640, 4);
        gnpm_k<<<gridg, blk>>>(bufp, i & 1);
        fin_k<<<10, 512>>>(cls_gw, cls_gb, box_gw, box_gb, i);
    }

    // heads (one launch): y=0,1 cls score tiles, y=2 box pred+ctr
    {
        P5 inC, inB;
        P5o outC{}, outB{};
        for (int l = 0; l < 5; l++) {
            inC.p[l] = lvl(0, 1, l);   // depth-3 outputs (pp = 3&1 = 1)
            inB.p[l] = lvl(1, 1, l);
        }
        dim3 gridh(358, 3, 2);
        convm_k<<<gridh, blk>>>(inC, inB, outC, outB,
            score_w, pred_w, score_b, pred_b, ctr_w, ctr_b,
            affs, affb, scales, out, sct, 1, 0);
    }
    mulfin_k<<<2 * TOT, 96>>>(out, sct);
}